// round 14
// baseline (speedup 1.0000x reference)
#include <cuda_runtime.h>
#include <cuda_bf16.h>
#include <cuda_fp16.h>
#include <math.h>
#include <stdint.h>

#define NN 100000
#define EE 1600000
#define HD 128
#define CD 40
#define NTILES 782            // ceil(NN/128)
#define PGRID 148             // persistent grid (1 CTA/SM)

// -------- scratch (static __device__ arrays; allocation forbidden) --------
__device__ __half g_hbuf[(size_t)NN * HD];  // GEMM out (gather src)
__device__ __half g_xh[(size_t)NN * HD];    // activation fp16 (GEMM in)
__device__ int    g_deg_out[NN];
__device__ int    g_deg_in[NN];
__device__ float  g_norm_out[NN];
__device__ float  g_norm_in[NN];
__device__ int    g_offs[NN + 1];
__device__ int    g_cursor[NN];
__device__ int    g_bsums[128];
__device__ int    g_csr[EE];

// Pre-built W operand tiles: [n][k] fp16, padded row stride 136 elems.
__device__ __align__(16) unsigned char g_B0h[128 * 136 * 2];
__device__ __align__(16) unsigned char g_B1h[128 * 136 * 2];
__device__ __align__(16) unsigned char g_B2h[64 * 136 * 2];

// ===========================================================================
// helpers (baseline sm_80 features -- no 'a'-gated PTX)
// ===========================================================================
__device__ __forceinline__ uint32_t smem_to_u32(const void* p) {
    uint32_t a;
    asm("{ .reg .u64 t; cvta.to.shared.u64 t, %1; cvt.u32.u64 %0, t; }"
        : "=r"(a) : "l"(p));
    return a;
}

#define LDSM4(r, addr) \
    asm volatile("ldmatrix.sync.aligned.m8n8.x4.shared.b16 {%0,%1,%2,%3}, [%4];" \
        : "=r"((r)[0]), "=r"((r)[1]), "=r"((r)[2]), "=r"((r)[3]) : "r"(addr))

#define MMA_F16(d, a, b0, b1) \
    asm volatile("mma.sync.aligned.m16n8k16.row.col.f32.f16.f16.f32 " \
        "{%0,%1,%2,%3}, {%4,%5,%6,%7}, {%8,%9}, {%0,%1,%2,%3};" \
        : "+f"((d)[0]), "+f"((d)[1]), "+f"((d)[2]), "+f"((d)[3]) \
        : "r"((a)[0]), "r"((a)[1]), "r"((a)[2]), "r"((a)[3]), "r"(b0), "r"(b1))

#define CP_ASYNC16(dst_u32, src_ptr) \
    asm volatile("cp.async.cg.shared.global [%0], [%1], 16;" \
        :: "r"(dst_u32), "l"(src_ptr) : "memory")
#define CP_COMMIT() asm volatile("cp.async.commit_group;" ::: "memory")
#define CP_WAIT0()  asm volatile("cp.async.wait_group 0;" ::: "memory")

// ===========================================================================
// Degrees + norms + CSR build
// ===========================================================================
__global__ void k_zero() {
    int i = blockIdx.x * blockDim.x + threadIdx.x;
    if (i < NN) { g_deg_out[i] = 0; g_deg_in[i] = 0; g_cursor[i] = 0; }
}

__global__ void k_deg(const int* __restrict__ src, const int* __restrict__ dst) {
    int e = blockIdx.x * blockDim.x + threadIdx.x;
    if (e < EE) {
        atomicAdd(&g_deg_out[src[e]], 1);
        atomicAdd(&g_deg_in[dst[e]], 1);
    }
}

// Fused: per-node norms + W-tile build ([n][k] fp16, stride 136)
__global__ void k_norm_wtiles(const float* __restrict__ W0,
                              const float* __restrict__ W1,
                              const float* __restrict__ W2) {
    int i = blockIdx.x * blockDim.x + threadIdx.x;
    if (i < NN) {
        int d0 = g_deg_out[i];
        int d1 = g_deg_in[i];
        g_norm_out[i] = d0 > 0 ? rsqrtf((float)d0) : 0.f;
        g_norm_in[i]  = d1 > 0 ? rsqrtf((float)d1) : 0.f;
    }
    if (i < 40960) {
        float val;
        unsigned char *ph;
        int n, k;
        if (i < 32768) {
            const float* W = (i < 16384) ? W0 : W1;
            ph = (i < 16384) ? g_B0h : g_B1h;
            int e = i & 16383;
            n = e >> 7; k = e & 127;
            val = W[k * 128 + n];
        } else {
            int e = i - 32768;
            n = e >> 7; k = e & 127;      // n in [0,64)
            val = (n < CD) ? W2[k * CD + n] : 0.f;
            ph = g_B2h;
        }
        uint32_t off = ((uint32_t)n * 136u + (uint32_t)k) * 2u;
        *(__half*)(ph + off) = __float2half_rn(val);
    }
}

// Convert input features fp32 -> fp16 buffer (one float4 per thread)
__global__ void k_feat(const float* __restrict__ feat) {
    size_t i = (size_t)blockIdx.x * blockDim.x + threadIdx.x;
    if (i >= (size_t)NN * 32) return;
    float4 v = ((const float4*)feat)[i];
    __half2 hp0 = __floats2half2_rn(v.x, v.y);
    __half2 hp1 = __floats2half2_rn(v.z, v.w);
    uint2 hv = make_uint2(*(uint32_t*)&hp0, *(uint32_t*)&hp1);
    ((uint2*)g_xh)[i] = hv;
}

__global__ void k_scan1() {
    __shared__ int sh[1024];
    int i = blockIdx.x * 1024 + threadIdx.x;
    int v = (i < NN) ? g_deg_in[i] : 0;
    sh[threadIdx.x] = v;
    __syncthreads();
    #pragma unroll
    for (int d = 1; d < 1024; d <<= 1) {
        int t = 0;
        if ((int)threadIdx.x >= d) t = sh[threadIdx.x - d];
        __syncthreads();
        sh[threadIdx.x] += t;
        __syncthreads();
    }
    if (i < NN) g_offs[i + 1] = sh[threadIdx.x];
    if (threadIdx.x == 1023) g_bsums[blockIdx.x] = sh[1023];
}

__global__ void k_scan2(int nb) {
    __shared__ int sh[128];
    int t = threadIdx.x;
    int v = (t < nb) ? g_bsums[t] : 0;
    sh[t] = v;
    __syncthreads();
    #pragma unroll
    for (int d = 1; d < 128; d <<= 1) {
        int x = 0;
        if (t >= d) x = sh[t - d];
        __syncthreads();
        sh[t] += x;
        __syncthreads();
    }
    if (t < nb) g_bsums[t] = sh[t] - v;   // exclusive
}

__global__ void k_scan3() {
    int i = blockIdx.x * blockDim.x + threadIdx.x;
    if (i == 0) g_offs[0] = 0;
    if (i < NN) g_offs[i + 1] += g_bsums[i >> 10];
}

__global__ void k_scatter(const int* __restrict__ src, const int* __restrict__ dst) {
    int e = blockIdx.x * blockDim.x + threadIdx.x;
    if (e < EE) {
        int d = dst[e];
        int pos = g_offs[d] + atomicAdd(&g_cursor[d], 1);
        g_csr[pos] = src[e];
    }
}

// ===========================================================================
// Persistent HMMA GEMM: hout[r,0:OUTC] = fp16(norm_out[r] * (x[r,:] @ W))
// SINGLE-TERM fp16: D = A*B (fp32 accumulate). cp.async double-buffered X.
// ===========================================================================
template <int NTILE, int OUTC>
__global__ void __launch_bounds__(512)
gemm_pers(const __half* __restrict__ xh,
          const unsigned char* __restrict__ Wh,
          __half* __restrict__ hout) {
    extern __shared__ __align__(16) unsigned char sm[];
    constexpr int XS     = 136;
    constexpr int XBUF   = 128 * XS * 2;
    constexpr int W_OFF  = 2 * XBUF;
    constexpr int WBYTES = NTILE * XS * 2;
    constexpr int NWTILE = NTILE / 4;
    constexpr int NFRAG  = NWTILE / 8;
    constexpr int NF2    = NFRAG / 2;

    const int tid  = threadIdx.x;
    const int wid  = tid >> 5;
    const int lane = tid & 31;
    const uint32_t smb = smem_to_u32(sm);

    const int pr = tid >> 2;
    const int ph = tid & 3;
    const uint32_t prel = (uint32_t)((pr * XS + ph * 32) * 2);

    auto prefetch = [&](int t, int buf) {
        const uint32_t base = smb + buf * XBUF;
        int gr = t * 128 + pr;
        if (gr < NN) {
            const __half* sh_ = &xh[(size_t)gr * 128 + ph * 32];
            #pragma unroll
            for (int i = 0; i < 4; i++)
                CP_ASYNC16(base + prel + i * 16, sh_ + i * 8);
        } else {
            uint4 z = make_uint4(0, 0, 0, 0);
            #pragma unroll
            for (int i = 0; i < 4; i++)
                *(uint4*)(sm + buf * XBUF + prel + i * 16) = z;
        }
    };

    prefetch(blockIdx.x, 0);
    CP_COMMIT();

    {
        const float4* s4h = (const float4*)Wh;
        float4* d4h = (float4*)(sm + W_OFF);
        for (int i = tid; i < WBYTES / 16; i += 512) d4h[i] = s4h[i];
    }

    const int m0 = (wid & 3) * 32;
    const int n0 = (wid >> 2) * NWTILE;
    const uint32_t aRel =
        (uint32_t)(((m0 + (lane & 15)) * XS + (lane >> 4) * 8) * 2);
    const uint32_t bH0 = smb + W_OFF +
        (uint32_t)(((n0 + (lane >> 4) * 8 + (lane & 7)) * XS + ((lane >> 3) & 1) * 8) * 2);

    const int g  = lane >> 2;
    const int tq = lane & 3;

    int buf = 0;
    for (int t = blockIdx.x; t < NTILES; t += gridDim.x, buf ^= 1) {
        const int row0 = t * 128;

        CP_WAIT0();
        __syncthreads();

        {
            int tn = t + gridDim.x;
            if (tn < NTILES) prefetch(tn, buf ^ 1);
            CP_COMMIT();
        }

        float acc[2][NFRAG][4];
        #pragma unroll
        for (int mi = 0; mi < 2; mi++)
            #pragma unroll
            for (int f = 0; f < NFRAG; f++)
                #pragma unroll
                for (int q = 0; q < 4; q++) acc[mi][f][q] = 0.f;

        uint32_t AHf[2][2][4];
        uint32_t BHf[2][NF2][4];

        uint32_t aH = smb + buf * XBUF + aRel;
        uint32_t bH = bH0;
        LDSM4(AHf[0][0], aH);
        LDSM4(AHf[0][1], aH + 16 * XS * 2);
        #pragma unroll
        for (int j = 0; j < NF2; j++)
            LDSM4(BHf[0][j], bH + j * 16 * XS * 2);

        #pragma unroll
        for (int ks = 0; ks < 8; ks++) {
            const int cur = ks & 1;
            const int nxt = cur ^ 1;
            if (ks < 7) {
                aH += 32; bH += 32;
                LDSM4(AHf[nxt][0], aH);
                LDSM4(AHf[nxt][1], aH + 16 * XS * 2);
                #pragma unroll
                for (int j = 0; j < NF2; j++)
                    LDSM4(BHf[nxt][j], bH + j * 16 * XS * 2);
            }
            #pragma unroll
            for (int mi = 0; mi < 2; mi++)
                #pragma unroll
                for (int j = 0; j < NF2; j++)
                    #pragma unroll
                    for (int h = 0; h < 2; h++)
                        MMA_F16(acc[mi][j * 2 + h], AHf[cur][mi],
                                BHf[cur][j][h * 2], BHf[cur][j][h * 2 + 1]);
        }

        #pragma unroll
        for (int mi = 0; mi < 2; mi++) {
            int r1 = row0 + m0 + mi * 16 + g;
            int r2 = r1 + 8;
            float s1 = (r1 < NN) ? g_norm_out[r1] : 0.f;
            float s2 = (r2 < NN) ? g_norm_out[r2] : 0.f;
            #pragma unroll
            for (int f = 0; f < NFRAG; f++) {
                int n = n0 + f * 8 + tq * 2;
                if (OUTC < NTILE && n >= OUTC) continue;
                float* c = acc[mi][f];
                if (r1 < NN) {
                    __half2 hv = __floats2half2_rn(c[0] * s1, c[1] * s1);
                    *(__half2*)&hout[(size_t)r1 * OUTC + n] = hv;
                }
                if (r2 < NN) {
                    __half2 hv = __floats2half2_rn(c[2] * s2, c[3] * s2);
                    *(__half2*)&hout[(size_t)r2 * OUTC + n] = hv;
                }
            }
        }
    }
}

// ===========================================================================
// Aggregation 128-dim: one warp per dst node. HIGH-MLP gather:
// 32 CSR indices loaded coalesced, distributed by shfl; 8 independent
// gathers in flight per group (no index->address dependency chain).
// ===========================================================================
__global__ void __launch_bounds__(256)
agg128(const float* __restrict__ bias) {
    int w = (blockIdx.x * blockDim.x + threadIdx.x) >> 5;
    if (w >= NN) return;
    int lane = threadIdx.x & 31;
    int beg = g_offs[w], end = g_offs[w + 1];

    float4 acc = make_float4(0.f, 0.f, 0.f, 0.f);
    for (int base = beg; base < end; base += 32) {
        int n = end - base;
        if (n > 32) n = 32;
        int myIdx = 0;
        if (base + lane < end) myIdx = g_csr[base + lane];

        for (int e = 0; e < n; e += 8) {
            uint2 u[8];
            #pragma unroll
            for (int j = 0; j < 8; j++) {
                int s = __shfl_sync(0xffffffffu, myIdx, e + j);
                u[j] = *(const uint2*)&g_hbuf[(size_t)s * 128 + lane * 4];
            }
            #pragma unroll
            for (int j = 0; j < 8; j++)
                if (e + j >= n) u[j] = make_uint2(0u, 0u);
            #pragma unroll
            for (int j = 0; j < 8; j++) {
                float2 a = __half22float2(*(__half2*)&u[j].x);
                float2 b = __half22float2(*(__half2*)&u[j].y);
                acc.x += a.x; acc.y += a.y; acc.z += b.x; acc.w += b.y;
            }
        }
    }

    float sc = g_norm_in[w];
    float4 b = *(const float4*)&bias[lane * 4];
    float4 o;
    o.x = fmaxf(fmaf(acc.x, sc, b.x), 0.f);
    o.y = fmaxf(fmaf(acc.y, sc, b.y), 0.f);
    o.z = fmaxf(fmaf(acc.z, sc, b.z), 0.f);
    o.w = fmaxf(fmaf(acc.w, sc, b.w), 0.f);

    __half2 hp0 = __floats2half2_rn(o.x, o.y);
    __half2 hp1 = __floats2half2_rn(o.z, o.w);
    uint2 hv = make_uint2(*(uint32_t*)&hp0, *(uint32_t*)&hp1);
    *(uint2*)&g_xh[(size_t)w * 128 + lane * 4] = hv;
}

// ===========================================================================
// Aggregation 40-dim (final layer, no relu) -> d_out (fp32). Same MLP-8 scheme.
// ===========================================================================
__global__ void __launch_bounds__(256)
agg40(const float* __restrict__ bias, float* __restrict__ out) {
    int w = (blockIdx.x * blockDim.x + threadIdx.x) >> 5;
    if (w >= NN) return;
    int lane = threadIdx.x & 31;
    int beg = g_offs[w], end = g_offs[w + 1];

    float2 acc = make_float2(0.f, 0.f);
    for (int base = beg; base < end; base += 32) {
        int n = end - base;
        if (n > 32) n = 32;
        int myIdx = 0;
        if (base + lane < end) myIdx = g_csr[base + lane];

        for (int e = 0; e < n; e += 8) {
            uint32_t u[8];
            #pragma unroll
            for (int j = 0; j < 8; j++) {
                int s = __shfl_sync(0xffffffffu, myIdx, e + j);
                u[j] = 0u;
                if (lane < 20)
                    u[j] = *(const uint32_t*)&g_hbuf[(size_t)s * 40 + lane * 2];
            }
            #pragma unroll
            for (int j = 0; j < 8; j++)
                if (e + j >= n) u[j] = 0u;
            #pragma unroll
            for (int j = 0; j < 8; j++) {
                float2 f = __half22float2(*(__half2*)&u[j]);
                acc.x += f.x; acc.y += f.y;
            }
        }
    }
    if (lane >= 20) return;
    float sc = g_norm_in[w];
    float2 o;
    o.x = fmaf(acc.x, sc, bias[lane * 2]);
    o.y = fmaf(acc.y, sc, bias[lane * 2 + 1]);
    *(float2*)&out[(size_t)w * 40 + lane * 2] = o;
}

// ===========================================================================
extern "C" void kernel_launch(void* const* d_in, const int* in_sizes, int n_in,
                              void* d_out, int out_size) {
    const float* feat = (const float*)d_in[0];
    const int*   src  = (const int*)  d_in[1];
    const int*   dst  = (const int*)  d_in[2];
    const float* W0   = (const float*)d_in[3];
    const float* b0   = (const float*)d_in[4];
    const float* W1   = (const float*)d_in[5];
    const float* b1   = (const float*)d_in[6];
    const float* W2   = (const float*)d_in[7];
    const float* b2   = (const float*)d_in[8];
    float* out = (float*)d_out;

    const int NB = (NN + 255) / 256;
    const int EB = (EE + 255) / 256;
    const int SB = (NN + 1023) / 1024;
    const int AGGB = (NN * 32 + 255) / 256;
    const int FB = (NN * 32 + 255) / 256;

    const int SMEM_BIG   = 2 * 128 * 136 * 2 + 128 * 136 * 2;  // 104448
    const int SMEM_SMALL = 2 * 128 * 136 * 2 + 64 * 136 * 2;   // 87040

    static cudaStream_t s2 = nullptr;
    static cudaEvent_t evF = nullptr, evJ = nullptr;
    static bool init_done = false;
    if (!init_done) {
        cudaFuncSetAttribute(gemm_pers<128, 128>,
                             cudaFuncAttributeMaxDynamicSharedMemorySize, SMEM_BIG);
        cudaFuncSetAttribute(gemm_pers<64, 40>,
                             cudaFuncAttributeMaxDynamicSharedMemorySize, SMEM_SMALL);
        cudaStreamCreateWithFlags(&s2, cudaStreamNonBlocking);
        cudaEventCreateWithFlags(&evF, cudaEventDisableTiming);
        cudaEventCreateWithFlags(&evJ, cudaEventDisableTiming);
        init_done = true;
    }

    unsigned char *p_B0h, *p_B1h, *p_B2h;
    cudaGetSymbolAddress((void**)&p_B0h, g_B0h);
    cudaGetSymbolAddress((void**)&p_B1h, g_B1h);
    cudaGetSymbolAddress((void**)&p_B2h, g_B2h);
    __half* p_hbuf;
    __half* p_xh;
    cudaGetSymbolAddress((void**)&p_hbuf, g_hbuf);
    cudaGetSymbolAddress((void**)&p_xh, g_xh);

    // common prep
    k_zero<<<NB, 256>>>();
    k_deg<<<EB, 256>>>(src, dst);
    k_norm_wtiles<<<NB, 256>>>(W0, W1, W2);

    // fork: feat-convert + layer-0 GEMM on s2, CSR build on main stream
    cudaEventRecord(evF, 0);
    cudaStreamWaitEvent(s2, evF, 0);
    k_feat<<<FB, 256, 0, s2>>>(feat);
    gemm_pers<128, 128><<<PGRID, 512, SMEM_BIG, s2>>>(p_xh, p_B0h, p_hbuf);
    k_scan1<<<SB, 1024>>>();
    k_scan2<<<1, 128>>>(SB);
    k_scan3<<<NB, 256>>>();
    k_scatter<<<EB, 256>>>(src, dst);
    cudaEventRecord(evJ, s2);
    cudaStreamWaitEvent(0, evJ, 0);

    // layer 0 aggregation (writes g_xh for next GEMM)
    agg128<<<AGGB, 256>>>(b0);
    // layer 1
    gemm_pers<128, 128><<<PGRID, 512, SMEM_BIG>>>(p_xh, p_B1h, p_hbuf);
    agg128<<<AGGB, 256>>>(b1);
    // layer 2
    gemm_pers<64, 40><<<PGRID, 512, SMEM_SMALL>>>(p_xh, p_B2h, p_hbuf);
    agg40<<<AGGB, 256>>>(b2, out);
}

// round 15
// speedup vs baseline: 1.0887x; 1.0887x over previous
#include <cuda_runtime.h>
#include <cuda_bf16.h>
#include <cuda_fp16.h>
#include <math.h>
#include <stdint.h>

#define NN 100000
#define EE 1600000
#define HD 128
#define CD 40
#define NTILES 782            // ceil(NN/128)
#define PGRID 148             // persistent grid (1 CTA/SM)
#define TSPLIT 391            // tile split for pipelining
#define WSPLIT (TSPLIT * 128) // node split (50048)

// -------- scratch (static __device__ arrays; allocation forbidden) --------
__device__ __half g_hbufA[(size_t)NN * HD];  // GEMM out buf A (layers 0,2)
__device__ __half g_hbufB[(size_t)NN * HD];  // GEMM out buf B (layer 1)
__device__ __half g_xh[(size_t)NN * HD];     // activation fp16 (GEMM in)
__device__ int    g_deg_out[NN];
__device__ int    g_deg_in[NN];
__device__ float  g_norm_out[NN];
__device__ float  g_norm_in[NN];
__device__ int    g_offs[NN + 1];
__device__ int    g_cursor[NN];
__device__ int    g_bsums[128];
__device__ int    g_csr[EE];

// Pre-built W operand tiles: [n][k] fp16, padded row stride 136 elems.
__device__ __align__(16) unsigned char g_B0h[128 * 136 * 2];
__device__ __align__(16) unsigned char g_B1h[128 * 136 * 2];
__device__ __align__(16) unsigned char g_B2h[64 * 136 * 2];

// ===========================================================================
// helpers (baseline sm_80 features -- no 'a'-gated PTX)
// ===========================================================================
__device__ __forceinline__ uint32_t smem_to_u32(const void* p) {
    uint32_t a;
    asm("{ .reg .u64 t; cvta.to.shared.u64 t, %1; cvt.u32.u64 %0, t; }"
        : "=r"(a) : "l"(p));
    return a;
}

#define LDSM4(r, addr) \
    asm volatile("ldmatrix.sync.aligned.m8n8.x4.shared.b16 {%0,%1,%2,%3}, [%4];" \
        : "=r"((r)[0]), "=r"((r)[1]), "=r"((r)[2]), "=r"((r)[3]) : "r"(addr))

#define MMA_F16(d, a, b0, b1) \
    asm volatile("mma.sync.aligned.m16n8k16.row.col.f32.f16.f16.f32 " \
        "{%0,%1,%2,%3}, {%4,%5,%6,%7}, {%8,%9}, {%0,%1,%2,%3};" \
        : "+f"((d)[0]), "+f"((d)[1]), "+f"((d)[2]), "+f"((d)[3]) \
        : "r"((a)[0]), "r"((a)[1]), "r"((a)[2]), "r"((a)[3]), "r"(b0), "r"(b1))

#define CP_ASYNC16(dst_u32, src_ptr) \
    asm volatile("cp.async.cg.shared.global [%0], [%1], 16;" \
        :: "r"(dst_u32), "l"(src_ptr) : "memory")
#define CP_COMMIT() asm volatile("cp.async.commit_group;" ::: "memory")
#define CP_WAIT0()  asm volatile("cp.async.wait_group 0;" ::: "memory")

// ===========================================================================
// Degrees + norms + CSR build
// ===========================================================================
__global__ void k_zero() {
    int i = blockIdx.x * blockDim.x + threadIdx.x;
    if (i < NN) { g_deg_out[i] = 0; g_deg_in[i] = 0; g_cursor[i] = 0; }
}

__global__ void k_deg(const int* __restrict__ src, const int* __restrict__ dst) {
    int e = blockIdx.x * blockDim.x + threadIdx.x;
    if (e < EE) {
        atomicAdd(&g_deg_out[src[e]], 1);
        atomicAdd(&g_deg_in[dst[e]], 1);
    }
}

// Fused: per-node norms + W-tile build ([n][k] fp16, stride 136)
__global__ void k_norm_wtiles(const float* __restrict__ W0,
                              const float* __restrict__ W1,
                              const float* __restrict__ W2) {
    int i = blockIdx.x * blockDim.x + threadIdx.x;
    if (i < NN) {
        int d0 = g_deg_out[i];
        int d1 = g_deg_in[i];
        g_norm_out[i] = d0 > 0 ? rsqrtf((float)d0) : 0.f;
        g_norm_in[i]  = d1 > 0 ? rsqrtf((float)d1) : 0.f;
    }
    if (i < 40960) {
        float val;
        unsigned char *ph;
        int n, k;
        if (i < 32768) {
            const float* W = (i < 16384) ? W0 : W1;
            ph = (i < 16384) ? g_B0h : g_B1h;
            int e = i & 16383;
            n = e >> 7; k = e & 127;
            val = W[k * 128 + n];
        } else {
            int e = i - 32768;
            n = e >> 7; k = e & 127;      // n in [0,64)
            val = (n < CD) ? W2[k * CD + n] : 0.f;
            ph = g_B2h;
        }
        uint32_t off = ((uint32_t)n * 136u + (uint32_t)k) * 2u;
        *(__half*)(ph + off) = __float2half_rn(val);
    }
}

// Convert input features fp32 -> fp16 buffer (one float4 per thread)
__global__ void k_feat(const float* __restrict__ feat) {
    size_t i = (size_t)blockIdx.x * blockDim.x + threadIdx.x;
    if (i >= (size_t)NN * 32) return;
    float4 v = ((const float4*)feat)[i];
    __half2 hp0 = __floats2half2_rn(v.x, v.y);
    __half2 hp1 = __floats2half2_rn(v.z, v.w);
    uint2 hv = make_uint2(*(uint32_t*)&hp0, *(uint32_t*)&hp1);
    ((uint2*)g_xh)[i] = hv;
}

__global__ void k_scan1() {
    __shared__ int sh[1024];
    int i = blockIdx.x * 1024 + threadIdx.x;
    int v = (i < NN) ? g_deg_in[i] : 0;
    sh[threadIdx.x] = v;
    __syncthreads();
    #pragma unroll
    for (int d = 1; d < 1024; d <<= 1) {
        int t = 0;
        if ((int)threadIdx.x >= d) t = sh[threadIdx.x - d];
        __syncthreads();
        sh[threadIdx.x] += t;
        __syncthreads();
    }
    if (i < NN) g_offs[i + 1] = sh[threadIdx.x];
    if (threadIdx.x == 1023) g_bsums[blockIdx.x] = sh[1023];
}

__global__ void k_scan2(int nb) {
    __shared__ int sh[128];
    int t = threadIdx.x;
    int v = (t < nb) ? g_bsums[t] : 0;
    sh[t] = v;
    __syncthreads();
    #pragma unroll
    for (int d = 1; d < 128; d <<= 1) {
        int x = 0;
        if (t >= d) x = sh[t - d];
        __syncthreads();
        sh[t] += x;
        __syncthreads();
    }
    if (t < nb) g_bsums[t] = sh[t] - v;   // exclusive
}

__global__ void k_scan3() {
    int i = blockIdx.x * blockDim.x + threadIdx.x;
    if (i == 0) g_offs[0] = 0;
    if (i < NN) g_offs[i + 1] += g_bsums[i >> 10];
}

__global__ void k_scatter(const int* __restrict__ src, const int* __restrict__ dst) {
    int e = blockIdx.x * blockDim.x + threadIdx.x;
    if (e < EE) {
        int d = dst[e];
        int pos = g_offs[d] + atomicAdd(&g_cursor[d], 1);
        g_csr[pos] = src[e];
    }
}

// ===========================================================================
// Persistent HMMA GEMM over tile range [tbeg, tend):
// hout[r,0:OUTC] = fp16(norm_out[r] * (x[r,:] @ W))
// SINGLE-TERM fp16, cp.async double-buffered X, one barrier per tile.
// ===========================================================================
template <int NTILE, int OUTC>
__global__ void __launch_bounds__(512)
gemm_pers(const __half* __restrict__ xh,
          const unsigned char* __restrict__ Wh,
          __half* __restrict__ hout,
          int tbeg, int tend) {
    extern __shared__ __align__(16) unsigned char sm[];
    constexpr int XS     = 136;
    constexpr int XBUF   = 128 * XS * 2;
    constexpr int W_OFF  = 2 * XBUF;
    constexpr int WBYTES = NTILE * XS * 2;
    constexpr int NWTILE = NTILE / 4;
    constexpr int NFRAG  = NWTILE / 8;
    constexpr int NF2    = NFRAG / 2;

    const int tid  = threadIdx.x;
    const int wid  = tid >> 5;
    const int lane = tid & 31;
    const uint32_t smb = smem_to_u32(sm);

    const int pr = tid >> 2;
    const int ph = tid & 3;
    const uint32_t prel = (uint32_t)((pr * XS + ph * 32) * 2);

    auto prefetch = [&](int t, int buf) {
        const uint32_t base = smb + buf * XBUF;
        int gr = t * 128 + pr;
        if (gr < NN) {
            const __half* sh_ = &xh[(size_t)gr * 128 + ph * 32];
            #pragma unroll
            for (int i = 0; i < 4; i++)
                CP_ASYNC16(base + prel + i * 16, sh_ + i * 8);
        } else {
            uint4 z = make_uint4(0, 0, 0, 0);
            #pragma unroll
            for (int i = 0; i < 4; i++)
                *(uint4*)(sm + buf * XBUF + prel + i * 16) = z;
        }
    };

    if (tbeg + (int)blockIdx.x < tend) prefetch(tbeg + blockIdx.x, 0);
    CP_COMMIT();

    {
        const float4* s4h = (const float4*)Wh;
        float4* d4h = (float4*)(sm + W_OFF);
        for (int i = tid; i < WBYTES / 16; i += 512) d4h[i] = s4h[i];
    }

    const int m0 = (wid & 3) * 32;
    const int n0 = (wid >> 2) * NWTILE;
    const uint32_t aRel =
        (uint32_t)(((m0 + (lane & 15)) * XS + (lane >> 4) * 8) * 2);
    const uint32_t bH0 = smb + W_OFF +
        (uint32_t)(((n0 + (lane >> 4) * 8 + (lane & 7)) * XS + ((lane >> 3) & 1) * 8) * 2);

    const int g  = lane >> 2;
    const int tq = lane & 3;

    int buf = 0;
    for (int t = tbeg + blockIdx.x; t < tend; t += gridDim.x, buf ^= 1) {
        const int row0 = t * 128;

        CP_WAIT0();
        __syncthreads();

        {
            int tn = t + gridDim.x;
            if (tn < tend) prefetch(tn, buf ^ 1);
            CP_COMMIT();
        }

        float acc[2][NFRAG][4];
        #pragma unroll
        for (int mi = 0; mi < 2; mi++)
            #pragma unroll
            for (int f = 0; f < NFRAG; f++)
                #pragma unroll
                for (int q = 0; q < 4; q++) acc[mi][f][q] = 0.f;

        uint32_t AHf[2][2][4];
        uint32_t BHf[2][NF2][4];

        uint32_t aH = smb + buf * XBUF + aRel;
        uint32_t bH = bH0;
        LDSM4(AHf[0][0], aH);
        LDSM4(AHf[0][1], aH + 16 * XS * 2);
        #pragma unroll
        for (int j = 0; j < NF2; j++)
            LDSM4(BHf[0][j], bH + j * 16 * XS * 2);

        #pragma unroll
        for (int ks = 0; ks < 8; ks++) {
            const int cur = ks & 1;
            const int nxt = cur ^ 1;
            if (ks < 7) {
                aH += 32; bH += 32;
                LDSM4(AHf[nxt][0], aH);
                LDSM4(AHf[nxt][1], aH + 16 * XS * 2);
                #pragma unroll
                for (int j = 0; j < NF2; j++)
                    LDSM4(BHf[nxt][j], bH + j * 16 * XS * 2);
            }
            #pragma unroll
            for (int mi = 0; mi < 2; mi++)
                #pragma unroll
                for (int j = 0; j < NF2; j++)
                    #pragma unroll
                    for (int h = 0; h < 2; h++)
                        MMA_F16(acc[mi][j * 2 + h], AHf[cur][mi],
                                BHf[cur][j][h * 2], BHf[cur][j][h * 2 + 1]);
        }

        #pragma unroll
        for (int mi = 0; mi < 2; mi++) {
            int r1 = row0 + m0 + mi * 16 + g;
            int r2 = r1 + 8;
            float s1 = (r1 < NN) ? g_norm_out[r1] : 0.f;
            float s2 = (r2 < NN) ? g_norm_out[r2] : 0.f;
            #pragma unroll
            for (int f = 0; f < NFRAG; f++) {
                int n = n0 + f * 8 + tq * 2;
                if (OUTC < NTILE && n >= OUTC) continue;
                float* c = acc[mi][f];
                if (r1 < NN) {
                    __half2 hv = __floats2half2_rn(c[0] * s1, c[1] * s1);
                    *(__half2*)&hout[(size_t)r1 * OUTC + n] = hv;
                }
                if (r2 < NN) {
                    __half2 hv = __floats2half2_rn(c[2] * s2, c[3] * s2);
                    *(__half2*)&hout[(size_t)r2 * OUTC + n] = hv;
                }
            }
        }
    }
}

// ===========================================================================
// Aggregation 128-dim over node range [wbeg, wend): one warp per dst node.
// R13-style 4-edge unrolled CSR gather (fp16 src), fp32 accum; fp16 out.
// ===========================================================================
__global__ void __launch_bounds__(256)
agg128(const float* __restrict__ bias, const __half* __restrict__ hsrc,
       int wbeg, int wend) {
    int w = wbeg + ((blockIdx.x * blockDim.x + threadIdx.x) >> 5);
    if (w >= wend) return;
    int lane = threadIdx.x & 31;
    int beg = g_offs[w], end = g_offs[w + 1];

    float4 acc = make_float4(0.f, 0.f, 0.f, 0.f);
    int e = beg;
    for (; e + 4 <= end; e += 4) {
        int s0 = g_csr[e],     s1 = g_csr[e + 1];
        int s2 = g_csr[e + 2], s3 = g_csr[e + 3];
        uint2 u0 = *(const uint2*)&hsrc[(size_t)s0 * 128 + lane * 4];
        uint2 u1 = *(const uint2*)&hsrc[(size_t)s1 * 128 + lane * 4];
        uint2 u2 = *(const uint2*)&hsrc[(size_t)s2 * 128 + lane * 4];
        uint2 u3 = *(const uint2*)&hsrc[(size_t)s3 * 128 + lane * 4];
        float2 a0 = __half22float2(*(__half2*)&u0.x), b0 = __half22float2(*(__half2*)&u0.y);
        float2 a1 = __half22float2(*(__half2*)&u1.x), b1 = __half22float2(*(__half2*)&u1.y);
        float2 a2 = __half22float2(*(__half2*)&u2.x), b2 = __half22float2(*(__half2*)&u2.y);
        float2 a3 = __half22float2(*(__half2*)&u3.x), b3 = __half22float2(*(__half2*)&u3.y);
        acc.x += (a0.x + a1.x) + (a2.x + a3.x);
        acc.y += (a0.y + a1.y) + (a2.y + a3.y);
        acc.z += (b0.x + b1.x) + (b2.x + b3.x);
        acc.w += (b0.y + b1.y) + (b2.y + b3.y);
    }
    for (; e < end; e++) {
        int s0 = g_csr[e];
        uint2 u0 = *(const uint2*)&hsrc[(size_t)s0 * 128 + lane * 4];
        float2 a0 = __half22float2(*(__half2*)&u0.x), b0 = __half22float2(*(__half2*)&u0.y);
        acc.x += a0.x; acc.y += a0.y; acc.z += b0.x; acc.w += b0.y;
    }

    float sc = g_norm_in[w];
    float4 b = *(const float4*)&bias[lane * 4];
    float4 o;
    o.x = fmaxf(fmaf(acc.x, sc, b.x), 0.f);
    o.y = fmaxf(fmaf(acc.y, sc, b.y), 0.f);
    o.z = fmaxf(fmaf(acc.z, sc, b.z), 0.f);
    o.w = fmaxf(fmaf(acc.w, sc, b.w), 0.f);

    __half2 hp0 = __floats2half2_rn(o.x, o.y);
    __half2 hp1 = __floats2half2_rn(o.z, o.w);
    uint2 hv = make_uint2(*(uint32_t*)&hp0, *(uint32_t*)&hp1);
    *(uint2*)&g_xh[(size_t)w * 128 + lane * 4] = hv;
}

// ===========================================================================
// Aggregation 40-dim (final layer, no relu) -> d_out (fp32). R13 form.
// ===========================================================================
__global__ void __launch_bounds__(256)
agg40(const float* __restrict__ bias, const __half* __restrict__ hsrc,
      float* __restrict__ out) {
    int w = (blockIdx.x * blockDim.x + threadIdx.x) >> 5;
    if (w >= NN) return;
    int lane = threadIdx.x & 31;
    int beg = g_offs[w], end = g_offs[w + 1];
    if (lane >= 20) return;

    float2 acc = make_float2(0.f, 0.f);
    int e = beg;
    for (; e + 2 <= end; e += 2) {
        int s0 = g_csr[e], s1 = g_csr[e + 1];
        __half2 h0 = *(const __half2*)&hsrc[(size_t)s0 * 40 + lane * 2];
        __half2 h1 = *(const __half2*)&hsrc[(size_t)s1 * 40 + lane * 2];
        float2 f0 = __half22float2(h0);
        float2 f1 = __half22float2(h1);
        acc.x += f0.x + f1.x;
        acc.y += f0.y + f1.y;
    }
    if (e < end) {
        int s0 = g_csr[e];
        float2 f0 = __half22float2(*(const __half2*)&hsrc[(size_t)s0 * 40 + lane * 2]);
        acc.x += f0.x; acc.y += f0.y;
    }
    float sc = g_norm_in[w];
    float2 o;
    o.x = fmaf(acc.x, sc, bias[lane * 2]);
    o.y = fmaf(acc.y, sc, bias[lane * 2 + 1]);
    *(float2*)&out[(size_t)w * 40 + lane * 2] = o;
}

// ===========================================================================
extern "C" void kernel_launch(void* const* d_in, const int* in_sizes, int n_in,
                              void* d_out, int out_size) {
    const float* feat = (const float*)d_in[0];
    const int*   src  = (const int*)  d_in[1];
    const int*   dst  = (const int*)  d_in[2];
    const float* W0   = (const float*)d_in[3];
    const float* b0   = (const float*)d_in[4];
    const float* W1   = (const float*)d_in[5];
    const float* b1   = (const float*)d_in[6];
    const float* W2   = (const float*)d_in[7];
    const float* b2   = (const float*)d_in[8];
    float* out = (float*)d_out;

    const int NB = (NN + 255) / 256;
    const int EB = (EE + 255) / 256;
    const int SB = (NN + 1023) / 1024;
    const int FB = (NN * 32 + 255) / 256;
    const int AGGB  = (NN * 32 + 255) / 256;
    const int AGH1  = (WSPLIT * 32 + 255) / 256;
    const int AGH2  = ((NN - WSPLIT) * 32 + 255) / 256;

    const int SMEM_BIG   = 2 * 128 * 136 * 2 + 128 * 136 * 2;  // 104448
    const int SMEM_SMALL = 2 * 128 * 136 * 2 + 64 * 136 * 2;   // 87040

    static cudaStream_t s2 = nullptr;
    static cudaEvent_t evF = nullptr, evJ = nullptr, evA = nullptr,
                       evB = nullptr, evC = nullptr, evD = nullptr;
    static bool init_done = false;
    if (!init_done) {
        cudaFuncSetAttribute(gemm_pers<128, 128>,
                             cudaFuncAttributeMaxDynamicSharedMemorySize, SMEM_BIG);
        cudaFuncSetAttribute(gemm_pers<64, 40>,
                             cudaFuncAttributeMaxDynamicSharedMemorySize, SMEM_SMALL);
        cudaStreamCreateWithFlags(&s2, cudaStreamNonBlocking);
        cudaEventCreateWithFlags(&evF, cudaEventDisableTiming);
        cudaEventCreateWithFlags(&evJ, cudaEventDisableTiming);
        cudaEventCreateWithFlags(&evA, cudaEventDisableTiming);
        cudaEventCreateWithFlags(&evB, cudaEventDisableTiming);
        cudaEventCreateWithFlags(&evC, cudaEventDisableTiming);
        cudaEventCreateWithFlags(&evD, cudaEventDisableTiming);
        init_done = true;
    }

    unsigned char *p_B0h, *p_B1h, *p_B2h;
    cudaGetSymbolAddress((void**)&p_B0h, g_B0h);
    cudaGetSymbolAddress((void**)&p_B1h, g_B1h);
    cudaGetSymbolAddress((void**)&p_B2h, g_B2h);
    __half *p_hA, *p_hB, *p_xh;
    cudaGetSymbolAddress((void**)&p_hA, g_hbufA);
    cudaGetSymbolAddress((void**)&p_hB, g_hbufB);
    cudaGetSymbolAddress((void**)&p_xh, g_xh);

    // common prep
    k_zero<<<NB, 256>>>();
    k_deg<<<EB, 256>>>(src, dst);
    k_norm_wtiles<<<NB, 256>>>(W0, W1, W2);

    // fork: feat-convert + layer-0 GEMM on s2, CSR build on main stream
    cudaEventRecord(evF, 0);
    cudaStreamWaitEvent(s2, evF, 0);
    k_feat<<<FB, 256, 0, s2>>>(feat);
    gemm_pers<128, 128><<<PGRID, 512, SMEM_BIG, s2>>>(p_xh, p_B0h, p_hA, 0, NTILES);
    k_scan1<<<SB, 1024>>>();
    k_scan2<<<1, 128>>>(SB);
    k_scan3<<<NB, 256>>>();
    k_scatter<<<EB, 256>>>(src, dst);
    cudaEventRecord(evJ, s2);
    cudaStreamWaitEvent(0, evJ, 0);

    // ---- layer 0 agg (reads hA, writes xh), pipelined with layer-1 GEMM ----
    agg128<<<AGH1, 256>>>(b0, p_hA, 0, WSPLIT);
    cudaEventRecord(evA, 0);
    agg128<<<AGH2, 256>>>(b0, p_hA, WSPLIT, NN);
    cudaStreamWaitEvent(s2, evA, 0);
    gemm_pers<128, 128><<<PGRID, 512, SMEM_BIG, s2>>>(p_xh, p_B1h, p_hB, 0, TSPLIT);
    gemm_pers<128, 128><<<PGRID, 512, SMEM_BIG>>>(p_xh, p_B1h, p_hB, TSPLIT, NTILES);
    cudaEventRecord(evB, s2);
    cudaStreamWaitEvent(0, evB, 0);

    // ---- layer 1 agg (reads hB, writes xh), pipelined with layer-2 GEMM ----
    agg128<<<AGH1, 256>>>(b1, p_hB, 0, WSPLIT);
    cudaEventRecord(evC, 0);
    agg128<<<AGH2, 256>>>(b1, p_hB, WSPLIT, NN);
    cudaStreamWaitEvent(s2, evC, 0);
    gemm_pers<64, 40><<<PGRID, 512, SMEM_SMALL, s2>>>(p_xh, p_B2h, p_hA, 0, TSPLIT);
    gemm_pers<64, 40><<<PGRID, 512, SMEM_SMALL>>>(p_xh, p_B2h, p_hA, TSPLIT, NTILES);
    cudaEventRecord(evD, s2);
    cudaStreamWaitEvent(0, evD, 0);

    // final aggregation -> output
    agg40<<<AGGB, 256>>>(b2, p_hA, out);
}

// round 16
// speedup vs baseline: 1.1462x; 1.0528x over previous
#include <cuda_runtime.h>
#include <cuda_bf16.h>
#include <cuda_fp16.h>
#include <math.h>
#include <stdint.h>

#define NN 100000
#define EE 1600000
#define HD 128
#define CD 40
#define NTILES 782            // ceil(NN/128)
#define PGRID 148             // persistent grid (1 CTA/SM)

// -------- scratch (static __device__ arrays; allocation forbidden) --------
__device__ __half g_hbuf[(size_t)NN * HD];  // GEMM out (gather src)
__device__ __half g_xh[(size_t)NN * HD];    // activation fp16 (GEMM in)
__device__ int    g_deg_out[NN];
__device__ int    g_deg_in[NN];
__device__ float  g_norm_out[NN];
__device__ float  g_norm_in[NN];
__device__ int    g_offs[NN + 1];
__device__ int    g_cursor[NN];
__device__ int    g_bsums[128];
__device__ int    g_csr[EE];

// Pre-built W operand tiles: [n][k] fp16, padded row stride 136 elems.
__device__ __align__(16) unsigned char g_B0h[128 * 136 * 2];
__device__ __align__(16) unsigned char g_B1h[128 * 136 * 2];
__device__ __align__(16) unsigned char g_B2h[64 * 136 * 2];

// ===========================================================================
// helpers (baseline sm_80 features -- no 'a'-gated PTX)
// ===========================================================================
__device__ __forceinline__ uint32_t smem_to_u32(const void* p) {
    uint32_t a;
    asm("{ .reg .u64 t; cvta.to.shared.u64 t, %1; cvt.u32.u64 %0, t; }"
        : "=r"(a) : "l"(p));
    return a;
}

#define LDSM4(r, addr) \
    asm volatile("ldmatrix.sync.aligned.m8n8.x4.shared.b16 {%0,%1,%2,%3}, [%4];" \
        : "=r"((r)[0]), "=r"((r)[1]), "=r"((r)[2]), "=r"((r)[3]) : "r"(addr))

#define MMA_F16(d, a, b0, b1) \
    asm volatile("mma.sync.aligned.m16n8k16.row.col.f32.f16.f16.f32 " \
        "{%0,%1,%2,%3}, {%4,%5,%6,%7}, {%8,%9}, {%0,%1,%2,%3};" \
        : "+f"((d)[0]), "+f"((d)[1]), "+f"((d)[2]), "+f"((d)[3]) \
        : "r"((a)[0]), "r"((a)[1]), "r"((a)[2]), "r"((a)[3]), "r"(b0), "r"(b1))

#define CP_ASYNC16(dst_u32, src_ptr) \
    asm volatile("cp.async.cg.shared.global [%0], [%1], 16;" \
        :: "r"(dst_u32), "l"(src_ptr) : "memory")
#define CP_COMMIT() asm volatile("cp.async.commit_group;" ::: "memory")
#define CP_WAIT0()  asm volatile("cp.async.wait_group 0;" ::: "memory")

// ===========================================================================
// Degrees + norms + CSR build
// ===========================================================================
__global__ void k_zero() {
    int i = blockIdx.x * blockDim.x + threadIdx.x;
    if (i < NN) { g_deg_out[i] = 0; g_deg_in[i] = 0; g_cursor[i] = 0; }
}

__global__ void k_deg(const int* __restrict__ src, const int* __restrict__ dst) {
    int e = blockIdx.x * blockDim.x + threadIdx.x;
    if (e < EE) {
        atomicAdd(&g_deg_out[src[e]], 1);
        atomicAdd(&g_deg_in[dst[e]], 1);
    }
}

// Fused: per-node norms + W-tile build ([n][k] fp16, stride 136)
__global__ void k_norm_wtiles(const float* __restrict__ W0,
                              const float* __restrict__ W1,
                              const float* __restrict__ W2) {
    int i = blockIdx.x * blockDim.x + threadIdx.x;
    if (i < NN) {
        int d0 = g_deg_out[i];
        int d1 = g_deg_in[i];
        g_norm_out[i] = d0 > 0 ? rsqrtf((float)d0) : 0.f;
        g_norm_in[i]  = d1 > 0 ? rsqrtf((float)d1) : 0.f;
    }
    if (i < 40960) {
        float val;
        unsigned char *ph;
        int n, k;
        if (i < 32768) {
            const float* W = (i < 16384) ? W0 : W1;
            ph = (i < 16384) ? g_B0h : g_B1h;
            int e = i & 16383;
            n = e >> 7; k = e & 127;
            val = W[k * 128 + n];
        } else {
            int e = i - 32768;
            n = e >> 7; k = e & 127;      // n in [0,64)
            val = (n < CD) ? W2[k * CD + n] : 0.f;
            ph = g_B2h;
        }
        uint32_t off = ((uint32_t)n * 136u + (uint32_t)k) * 2u;
        *(__half*)(ph + off) = __float2half_rn(val);
    }
}

// Convert input features fp32 -> fp16 buffer (one float4 per thread)
__global__ void k_feat(const float* __restrict__ feat) {
    size_t i = (size_t)blockIdx.x * blockDim.x + threadIdx.x;
    if (i >= (size_t)NN * 32) return;
    float4 v = ((const float4*)feat)[i];
    __half2 hp0 = __floats2half2_rn(v.x, v.y);
    __half2 hp1 = __floats2half2_rn(v.z, v.w);
    uint2 hv = make_uint2(*(uint32_t*)&hp0, *(uint32_t*)&hp1);
    ((uint2*)g_xh)[i] = hv;
}

__global__ void k_scan1() {
    __shared__ int sh[1024];
    int i = blockIdx.x * 1024 + threadIdx.x;
    int v = (i < NN) ? g_deg_in[i] : 0;
    sh[threadIdx.x] = v;
    __syncthreads();
    #pragma unroll
    for (int d = 1; d < 1024; d <<= 1) {
        int t = 0;
        if ((int)threadIdx.x >= d) t = sh[threadIdx.x - d];
        __syncthreads();
        sh[threadIdx.x] += t;
        __syncthreads();
    }
    if (i < NN) g_offs[i + 1] = sh[threadIdx.x];
    if (threadIdx.x == 1023) g_bsums[blockIdx.x] = sh[1023];
}

__global__ void k_scan2(int nb) {
    __shared__ int sh[128];
    int t = threadIdx.x;
    int v = (t < nb) ? g_bsums[t] : 0;
    sh[t] = v;
    __syncthreads();
    #pragma unroll
    for (int d = 1; d < 128; d <<= 1) {
        int x = 0;
        if (t >= d) x = sh[t - d];
        __syncthreads();
        sh[t] += x;
        __syncthreads();
    }
    if (t < nb) g_bsums[t] = sh[t] - v;   // exclusive
}

__global__ void k_scan3() {
    int i = blockIdx.x * blockDim.x + threadIdx.x;
    if (i == 0) g_offs[0] = 0;
    if (i < NN) g_offs[i + 1] += g_bsums[i >> 10];
}

__global__ void k_scatter(const int* __restrict__ src, const int* __restrict__ dst) {
    int e = blockIdx.x * blockDim.x + threadIdx.x;
    if (e < EE) {
        int d = dst[e];
        int pos = g_offs[d] + atomicAdd(&g_cursor[d], 1);
        g_csr[pos] = src[e];
    }
}

// ===========================================================================
// Persistent HMMA GEMM: hout[r,0:OUTC] = fp16(norm_out[r] * (x[r,:] @ W))
// SINGLE-TERM fp16: D = A*B (fp32 accumulate). cp.async double-buffered X.
// ===========================================================================
template <int NTILE, int OUTC>
__global__ void __launch_bounds__(512)
gemm_pers(const __half* __restrict__ xh,
          const unsigned char* __restrict__ Wh,
          __half* __restrict__ hout) {
    extern __shared__ __align__(16) unsigned char sm[];
    constexpr int XS     = 136;
    constexpr int XBUF   = 128 * XS * 2;
    constexpr int W_OFF  = 2 * XBUF;
    constexpr int WBYTES = NTILE * XS * 2;
    constexpr int NWTILE = NTILE / 4;
    constexpr int NFRAG  = NWTILE / 8;
    constexpr int NF2    = NFRAG / 2;

    const int tid  = threadIdx.x;
    const int wid  = tid >> 5;
    const int lane = tid & 31;
    const uint32_t smb = smem_to_u32(sm);

    const int pr = tid >> 2;
    const int ph = tid & 3;
    const uint32_t prel = (uint32_t)((pr * XS + ph * 32) * 2);

    auto prefetch = [&](int t, int buf) {
        const uint32_t base = smb + buf * XBUF;
        int gr = t * 128 + pr;
        if (gr < NN) {
            const __half* sh_ = &xh[(size_t)gr * 128 + ph * 32];
            #pragma unroll
            for (int i = 0; i < 4; i++)
                CP_ASYNC16(base + prel + i * 16, sh_ + i * 8);
        } else {
            uint4 z = make_uint4(0, 0, 0, 0);
            #pragma unroll
            for (int i = 0; i < 4; i++)
                *(uint4*)(sm + buf * XBUF + prel + i * 16) = z;
        }
    };

    prefetch(blockIdx.x, 0);
    CP_COMMIT();

    {
        const float4* s4h = (const float4*)Wh;
        float4* d4h = (float4*)(sm + W_OFF);
        for (int i = tid; i < WBYTES / 16; i += 512) d4h[i] = s4h[i];
    }

    const int m0 = (wid & 3) * 32;
    const int n0 = (wid >> 2) * NWTILE;
    const uint32_t aRel =
        (uint32_t)(((m0 + (lane & 15)) * XS + (lane >> 4) * 8) * 2);
    const uint32_t bH0 = smb + W_OFF +
        (uint32_t)(((n0 + (lane >> 4) * 8 + (lane & 7)) * XS + ((lane >> 3) & 1) * 8) * 2);

    const int g  = lane >> 2;
    const int tq = lane & 3;

    int buf = 0;
    for (int t = blockIdx.x; t < NTILES; t += gridDim.x, buf ^= 1) {
        const int row0 = t * 128;

        CP_WAIT0();
        __syncthreads();

        {
            int tn = t + gridDim.x;
            if (tn < NTILES) prefetch(tn, buf ^ 1);
            CP_COMMIT();
        }

        float acc[2][NFRAG][4];
        #pragma unroll
        for (int mi = 0; mi < 2; mi++)
            #pragma unroll
            for (int f = 0; f < NFRAG; f++)
                #pragma unroll
                for (int q = 0; q < 4; q++) acc[mi][f][q] = 0.f;

        uint32_t AHf[2][2][4];
        uint32_t BHf[2][NF2][4];

        uint32_t aH = smb + buf * XBUF + aRel;
        uint32_t bH = bH0;
        LDSM4(AHf[0][0], aH);
        LDSM4(AHf[0][1], aH + 16 * XS * 2);
        #pragma unroll
        for (int j = 0; j < NF2; j++)
            LDSM4(BHf[0][j], bH + j * 16 * XS * 2);

        #pragma unroll
        for (int ks = 0; ks < 8; ks++) {
            const int cur = ks & 1;
            const int nxt = cur ^ 1;
            if (ks < 7) {
                aH += 32; bH += 32;
                LDSM4(AHf[nxt][0], aH);
                LDSM4(AHf[nxt][1], aH + 16 * XS * 2);
                #pragma unroll
                for (int j = 0; j < NF2; j++)
                    LDSM4(BHf[nxt][j], bH + j * 16 * XS * 2);
            }
            #pragma unroll
            for (int mi = 0; mi < 2; mi++)
                #pragma unroll
                for (int j = 0; j < NF2; j++)
                    #pragma unroll
                    for (int h = 0; h < 2; h++)
                        MMA_F16(acc[mi][j * 2 + h], AHf[cur][mi],
                                BHf[cur][j][h * 2], BHf[cur][j][h * 2 + 1]);
        }

        #pragma unroll
        for (int mi = 0; mi < 2; mi++) {
            int r1 = row0 + m0 + mi * 16 + g;
            int r2 = r1 + 8;
            float s1 = (r1 < NN) ? g_norm_out[r1] : 0.f;
            float s2 = (r2 < NN) ? g_norm_out[r2] : 0.f;
            #pragma unroll
            for (int f = 0; f < NFRAG; f++) {
                int n = n0 + f * 8 + tq * 2;
                if (OUTC < NTILE && n >= OUTC) continue;
                float* c = acc[mi][f];
                if (r1 < NN) {
                    __half2 hv = __floats2half2_rn(c[0] * s1, c[1] * s1);
                    *(__half2*)&hout[(size_t)r1 * OUTC + n] = hv;
                }
                if (r2 < NN) {
                    __half2 hv = __floats2half2_rn(c[2] * s2, c[3] * s2);
                    *(__half2*)&hout[(size_t)r2 * OUTC + n] = hv;
                }
            }
        }
    }
}

// ===========================================================================
// Aggregation 128-dim: one warp per dst node, PAIR-EDGE layout.
// lanes 0-15 -> edge e, lanes 16-31 -> edge e+1; each lane gathers uint4
// (8 dims). One index LDG + one gather LDG serve TWO edges. fp32 accum,
// cross-half shfl reduce, lanes 0-15 store 8 dims (16B).
// ===========================================================================
__global__ void __launch_bounds__(256)
agg128(const float* __restrict__ bias, const __half* __restrict__ hsrc) {
    int w = (blockIdx.x * blockDim.x + threadIdx.x) >> 5;
    if (w >= NN) return;
    const int lane = threadIdx.x & 31;
    const int half = lane >> 4;        // 0 or 1
    const int hl   = lane & 15;        // dim block (8 dims each)
    const int beg = g_offs[w], end = g_offs[w + 1];

    float acc[8];
    #pragma unroll
    for (int j = 0; j < 8; j++) acc[j] = 0.f;

    int e = beg;
    // 4 edges per iter: two independent pair-gathers in flight
    for (; e + 4 <= end; e += 4) {
        int sA = g_csr[e + half];
        int sB = g_csr[e + 2 + half];
        uint4 uA = *(const uint4*)&hsrc[(size_t)sA * 128 + hl * 8];
        uint4 uB = *(const uint4*)&hsrc[(size_t)sB * 128 + hl * 8];
        float2 f0 = __half22float2(*(__half2*)&uA.x);
        float2 f1 = __half22float2(*(__half2*)&uA.y);
        float2 f2 = __half22float2(*(__half2*)&uA.z);
        float2 f3 = __half22float2(*(__half2*)&uA.w);
        float2 g0 = __half22float2(*(__half2*)&uB.x);
        float2 g1 = __half22float2(*(__half2*)&uB.y);
        float2 g2 = __half22float2(*(__half2*)&uB.z);
        float2 g3 = __half22float2(*(__half2*)&uB.w);
        acc[0] += f0.x + g0.x; acc[1] += f0.y + g0.y;
        acc[2] += f1.x + g1.x; acc[3] += f1.y + g1.y;
        acc[4] += f2.x + g2.x; acc[5] += f2.y + g2.y;
        acc[6] += f3.x + g3.x; acc[7] += f3.y + g3.y;
    }
    // 2-edge tail
    if (e + 2 <= end) {
        int sA = g_csr[e + half];
        uint4 uA = *(const uint4*)&hsrc[(size_t)sA * 128 + hl * 8];
        float2 f0 = __half22float2(*(__half2*)&uA.x);
        float2 f1 = __half22float2(*(__half2*)&uA.y);
        float2 f2 = __half22float2(*(__half2*)&uA.z);
        float2 f3 = __half22float2(*(__half2*)&uA.w);
        acc[0] += f0.x; acc[1] += f0.y; acc[2] += f1.x; acc[3] += f1.y;
        acc[4] += f2.x; acc[5] += f2.y; acc[6] += f3.x; acc[7] += f3.y;
        e += 2;
    }
    // 1-edge tail (lanes 0-15 only)
    if (e < end && half == 0) {
        int sA = g_csr[e];
        uint4 uA = *(const uint4*)&hsrc[(size_t)sA * 128 + hl * 8];
        float2 f0 = __half22float2(*(__half2*)&uA.x);
        float2 f1 = __half22float2(*(__half2*)&uA.y);
        float2 f2 = __half22float2(*(__half2*)&uA.z);
        float2 f3 = __half22float2(*(__half2*)&uA.w);
        acc[0] += f0.x; acc[1] += f0.y; acc[2] += f1.x; acc[3] += f1.y;
        acc[4] += f2.x; acc[5] += f2.y; acc[6] += f3.x; acc[7] += f3.y;
    }

    // cross-half reduce
    #pragma unroll
    for (int j = 0; j < 8; j++)
        acc[j] += __shfl_xor_sync(0xffffffffu, acc[j], 16);

    if (half == 0) {
        float sc = g_norm_in[w];
        float4 b0 = *(const float4*)&bias[hl * 8];
        float4 b1 = *(const float4*)&bias[hl * 8 + 4];
        float o0 = fmaxf(fmaf(acc[0], sc, b0.x), 0.f);
        float o1 = fmaxf(fmaf(acc[1], sc, b0.y), 0.f);
        float o2 = fmaxf(fmaf(acc[2], sc, b0.z), 0.f);
        float o3 = fmaxf(fmaf(acc[3], sc, b0.w), 0.f);
        float o4 = fmaxf(fmaf(acc[4], sc, b1.x), 0.f);
        float o5 = fmaxf(fmaf(acc[5], sc, b1.y), 0.f);
        float o6 = fmaxf(fmaf(acc[6], sc, b1.z), 0.f);
        float o7 = fmaxf(fmaf(acc[7], sc, b1.w), 0.f);
        __half2 h0 = __floats2half2_rn(o0, o1);
        __half2 h1 = __floats2half2_rn(o2, o3);
        __half2 h2 = __floats2half2_rn(o4, o5);
        __half2 h3 = __floats2half2_rn(o6, o7);
        uint4 hv = make_uint4(*(uint32_t*)&h0, *(uint32_t*)&h1,
                              *(uint32_t*)&h2, *(uint32_t*)&h3);
        *(uint4*)&g_xh[(size_t)w * 128 + hl * 8] = hv;
    }
}

// ===========================================================================
// Aggregation 40-dim (final layer, no relu) -> d_out (fp32). R13 form.
// ===========================================================================
__global__ void __launch_bounds__(256)
agg40(const float* __restrict__ bias, const __half* __restrict__ hsrc,
      float* __restrict__ out) {
    int w = (blockIdx.x * blockDim.x + threadIdx.x) >> 5;
    if (w >= NN) return;
    int lane = threadIdx.x & 31;
    int beg = g_offs[w], end = g_offs[w + 1];
    if (lane >= 20) return;

    float2 acc = make_float2(0.f, 0.f);
    int e = beg;
    for (; e + 2 <= end; e += 2) {
        int s0 = g_csr[e], s1 = g_csr[e + 1];
        __half2 h0 = *(const __half2*)&hsrc[(size_t)s0 * 40 + lane * 2];
        __half2 h1 = *(const __half2*)&hsrc[(size_t)s1 * 40 + lane * 2];
        float2 f0 = __half22float2(h0);
        float2 f1 = __half22float2(h1);
        acc.x += f0.x + f1.x;
        acc.y += f0.y + f1.y;
    }
    if (e < end) {
        int s0 = g_csr[e];
        float2 f0 = __half22float2(*(const __half2*)&hsrc[(size_t)s0 * 40 + lane * 2]);
        acc.x += f0.x; acc.y += f0.y;
    }
    float sc = g_norm_in[w];
    float2 o;
    o.x = fmaf(acc.x, sc, bias[lane * 2]);
    o.y = fmaf(acc.y, sc, bias[lane * 2 + 1]);
    *(float2*)&out[(size_t)w * 40 + lane * 2] = o;
}

// ===========================================================================
extern "C" void kernel_launch(void* const* d_in, const int* in_sizes, int n_in,
                              void* d_out, int out_size) {
    const float* feat = (const float*)d_in[0];
    const int*   src  = (const int*)  d_in[1];
    const int*   dst  = (const int*)  d_in[2];
    const float* W0   = (const float*)d_in[3];
    const float* b0   = (const float*)d_in[4];
    const float* W1   = (const float*)d_in[5];
    const float* b1   = (const float*)d_in[6];
    const float* W2   = (const float*)d_in[7];
    const float* b2   = (const float*)d_in[8];
    float* out = (float*)d_out;

    const int NB = (NN + 255) / 256;
    const int EB = (EE + 255) / 256;
    const int SB = (NN + 1023) / 1024;
    const int AGGB = (NN * 32 + 255) / 256;
    const int FB = (NN * 32 + 255) / 256;

    const int SMEM_BIG   = 2 * 128 * 136 * 2 + 128 * 136 * 2;  // 104448
    const int SMEM_SMALL = 2 * 128 * 136 * 2 + 64 * 136 * 2;   // 87040

    static cudaStream_t s2 = nullptr;
    static cudaEvent_t evF = nullptr, evJ = nullptr;
    static bool init_done = false;
    if (!init_done) {
        cudaFuncSetAttribute(gemm_pers<128, 128>,
                             cudaFuncAttributeMaxDynamicSharedMemorySize, SMEM_BIG);
        cudaFuncSetAttribute(gemm_pers<64, 40>,
                             cudaFuncAttributeMaxDynamicSharedMemorySize, SMEM_SMALL);
        cudaStreamCreateWithFlags(&s2, cudaStreamNonBlocking);
        cudaEventCreateWithFlags(&evF, cudaEventDisableTiming);
        cudaEventCreateWithFlags(&evJ, cudaEventDisableTiming);
        init_done = true;
    }

    unsigned char *p_B0h, *p_B1h, *p_B2h;
    cudaGetSymbolAddress((void**)&p_B0h, g_B0h);
    cudaGetSymbolAddress((void**)&p_B1h, g_B1h);
    cudaGetSymbolAddress((void**)&p_B2h, g_B2h);
    __half* p_hbuf;
    __half* p_xh;
    cudaGetSymbolAddress((void**)&p_hbuf, g_hbuf);
    cudaGetSymbolAddress((void**)&p_xh, g_xh);

    // common prep
    k_zero<<<NB, 256>>>();
    k_deg<<<EB, 256>>>(src, dst);
    k_norm_wtiles<<<NB, 256>>>(W0, W1, W2);

    // fork: feat-convert + layer-0 GEMM on s2, CSR build on main stream
    cudaEventRecord(evF, 0);
    cudaStreamWaitEvent(s2, evF, 0);
    k_feat<<<FB, 256, 0, s2>>>(feat);
    gemm_pers<128, 128><<<PGRID, 512, SMEM_BIG, s2>>>(p_xh, p_B0h, p_hbuf);
    k_scan1<<<SB, 1024>>>();
    k_scan2<<<1, 128>>>(SB);
    k_scan3<<<NB, 256>>>();
    k_scatter<<<EB, 256>>>(src, dst);
    cudaEventRecord(evJ, s2);
    cudaStreamWaitEvent(0, evJ, 0);

    // layer 0 aggregation (writes g_xh for next GEMM)
    agg128<<<AGGB, 256>>>(b0, p_hbuf);
    // layer 1
    gemm_pers<128, 128><<<PGRID, 512, SMEM_BIG>>>(p_xh, p_B1h, p_hbuf);
    agg128<<<AGGB, 256>>>(b1, p_hbuf);
    // layer 2
    gemm_pers<64, 40><<<PGRID, 512, SMEM_SMALL>>>(p_xh, p_B2h, p_hbuf);
    agg40<<<AGGB, 256>>>(b2, p_hbuf, out);
}

// round 17
// speedup vs baseline: 1.2324x; 1.0752x over previous
#include <cuda_runtime.h>
#include <cuda_bf16.h>
#include <cuda_fp16.h>
#include <math.h>
#include <stdint.h>

#define NN 100000
#define EE 1600000
#define HD 128
#define CD 40
#define NTILES 782            // ceil(NN/128)
#define PGRID 148             // persistent grid (1 CTA/SM)

// -------- scratch (static __device__ arrays; allocation forbidden) --------
__device__ __half g_hbuf[(size_t)NN * HD];  // GEMM out (gather src)
__device__ __half g_xh[(size_t)NN * HD];    // activation fp16 (GEMM in)
__device__ int    g_deg_out[NN];
__device__ int    g_deg_in[NN];
__device__ float  g_norm_out[NN];
__device__ float  g_norm_in[NN];
__device__ int    g_offs[NN + 1];
__device__ int    g_cursor[NN];
__device__ int    g_bsums[128];
__device__ int    g_csr[EE];

// Pre-built W operand tiles: [n][k] fp16, padded row stride 136 elems.
__device__ __align__(16) unsigned char g_B0h[128 * 136 * 2];
__device__ __align__(16) unsigned char g_B1h[128 * 136 * 2];
__device__ __align__(16) unsigned char g_B2h[64 * 136 * 2];

// ===========================================================================
// helpers (baseline sm_80 features -- no 'a'-gated PTX)
// ===========================================================================
__device__ __forceinline__ uint32_t smem_to_u32(const void* p) {
    uint32_t a;
    asm("{ .reg .u64 t; cvta.to.shared.u64 t, %1; cvt.u32.u64 %0, t; }"
        : "=r"(a) : "l"(p));
    return a;
}

#define LDSM4(r, addr) \
    asm volatile("ldmatrix.sync.aligned.m8n8.x4.shared.b16 {%0,%1,%2,%3}, [%4];" \
        : "=r"((r)[0]), "=r"((r)[1]), "=r"((r)[2]), "=r"((r)[3]) : "r"(addr))

#define MMA_F16(d, a, b0, b1) \
    asm volatile("mma.sync.aligned.m16n8k16.row.col.f32.f16.f16.f32 " \
        "{%0,%1,%2,%3}, {%4,%5,%6,%7}, {%8,%9}, {%0,%1,%2,%3};" \
        : "+f"((d)[0]), "+f"((d)[1]), "+f"((d)[2]), "+f"((d)[3]) \
        : "r"((a)[0]), "r"((a)[1]), "r"((a)[2]), "r"((a)[3]), "r"(b0), "r"(b1))

#define CP_ASYNC16(dst_u32, src_ptr) \
    asm volatile("cp.async.cg.shared.global [%0], [%1], 16;" \
        :: "r"(dst_u32), "l"(src_ptr) : "memory")
#define CP_COMMIT() asm volatile("cp.async.commit_group;" ::: "memory")
#define CP_WAIT0()  asm volatile("cp.async.wait_group 0;" ::: "memory")

// ===========================================================================
// Degrees + norms + CSR build
// ===========================================================================
__global__ void k_zero() {
    int i = blockIdx.x * blockDim.x + threadIdx.x;
    if (i < NN) { g_deg_out[i] = 0; g_deg_in[i] = 0; g_cursor[i] = 0; }
}

__global__ void k_deg(const int* __restrict__ src, const int* __restrict__ dst) {
    int e = blockIdx.x * blockDim.x + threadIdx.x;
    if (e < EE) {
        atomicAdd(&g_deg_out[src[e]], 1);
        atomicAdd(&g_deg_in[dst[e]], 1);
    }
}

// Per-node norms (depends on degrees)
__global__ void k_norm() {
    int i = blockIdx.x * blockDim.x + threadIdx.x;
    if (i < NN) {
        int d0 = g_deg_out[i];
        int d1 = g_deg_in[i];
        g_norm_out[i] = d0 > 0 ? rsqrtf((float)d0) : 0.f;
        g_norm_in[i]  = d1 > 0 ? rsqrtf((float)d1) : 0.f;
    }
}

// W-tile build ([n][k] fp16, stride 136) -- depends only on W inputs
__global__ void k_wtiles(const float* __restrict__ W0,
                         const float* __restrict__ W1,
                         const float* __restrict__ W2) {
    int i = blockIdx.x * blockDim.x + threadIdx.x;
    if (i >= 40960) return;
    float val;
    unsigned char *ph;
    int n, k;
    if (i < 32768) {
        const float* W = (i < 16384) ? W0 : W1;
        ph = (i < 16384) ? g_B0h : g_B1h;
        int e = i & 16383;
        n = e >> 7; k = e & 127;
        val = W[k * 128 + n];
    } else {
        int e = i - 32768;
        n = e >> 7; k = e & 127;      // n in [0,64)
        val = (n < CD) ? W2[k * CD + n] : 0.f;
        ph = g_B2h;
    }
    uint32_t off = ((uint32_t)n * 136u + (uint32_t)k) * 2u;
    *(__half*)(ph + off) = __float2half_rn(val);
}

// Convert input features fp32 -> fp16 buffer (one float4 per thread)
__global__ void k_feat(const float* __restrict__ feat) {
    size_t i = (size_t)blockIdx.x * blockDim.x + threadIdx.x;
    if (i >= (size_t)NN * 32) return;
    float4 v = ((const float4*)feat)[i];
    __half2 hp0 = __floats2half2_rn(v.x, v.y);
    __half2 hp1 = __floats2half2_rn(v.z, v.w);
    uint2 hv = make_uint2(*(uint32_t*)&hp0, *(uint32_t*)&hp1);
    ((uint2*)g_xh)[i] = hv;
}

__global__ void k_scan1() {
    __shared__ int sh[1024];
    int i = blockIdx.x * 1024 + threadIdx.x;
    int v = (i < NN) ? g_deg_in[i] : 0;
    sh[threadIdx.x] = v;
    __syncthreads();
    #pragma unroll
    for (int d = 1; d < 1024; d <<= 1) {
        int t = 0;
        if ((int)threadIdx.x >= d) t = sh[threadIdx.x - d];
        __syncthreads();
        sh[threadIdx.x] += t;
        __syncthreads();
    }
    if (i < NN) g_offs[i + 1] = sh[threadIdx.x];
    if (threadIdx.x == 1023) g_bsums[blockIdx.x] = sh[1023];
}

__global__ void k_scan2(int nb) {
    __shared__ int sh[128];
    int t = threadIdx.x;
    int v = (t < nb) ? g_bsums[t] : 0;
    sh[t] = v;
    __syncthreads();
    #pragma unroll
    for (int d = 1; d < 128; d <<= 1) {
        int x = 0;
        if (t >= d) x = sh[t - d];
        __syncthreads();
        sh[t] += x;
        __syncthreads();
    }
    if (t < nb) g_bsums[t] = sh[t] - v;   // exclusive
}

__global__ void k_scan3() {
    int i = blockIdx.x * blockDim.x + threadIdx.x;
    if (i == 0) g_offs[0] = 0;
    if (i < NN) g_offs[i + 1] += g_bsums[i >> 10];
}

__global__ void k_scatter(const int* __restrict__ src, const int* __restrict__ dst) {
    int e = blockIdx.x * blockDim.x + threadIdx.x;
    if (e < EE) {
        int d = dst[e];
        int pos = g_offs[d] + atomicAdd(&g_cursor[d], 1);
        g_csr[pos] = src[e];
    }
}

// ===========================================================================
// Persistent HMMA GEMM: hout[r,0:OUTC] = fp16(norm_out[r] * (x[r,:] @ W))
// SINGLE-TERM fp16: D = A*B (fp32 accumulate). cp.async double-buffered X.
// ===========================================================================
template <int NTILE, int OUTC>
__global__ void __launch_bounds__(512)
gemm_pers(const __half* __restrict__ xh,
          const unsigned char* __restrict__ Wh,
          __half* __restrict__ hout) {
    extern __shared__ __align__(16) unsigned char sm[];
    constexpr int XS     = 136;
    constexpr int XBUF   = 128 * XS * 2;
    constexpr int W_OFF  = 2 * XBUF;
    constexpr int WBYTES = NTILE * XS * 2;
    constexpr int NWTILE = NTILE / 4;
    constexpr int NFRAG  = NWTILE / 8;
    constexpr int NF2    = NFRAG / 2;

    const int tid  = threadIdx.x;
    const int wid  = tid >> 5;
    const int lane = tid & 31;
    const uint32_t smb = smem_to_u32(sm);

    const int pr = tid >> 2;
    const int ph = tid & 3;
    const uint32_t prel = (uint32_t)((pr * XS + ph * 32) * 2);

    auto prefetch = [&](int t, int buf) {
        const uint32_t base = smb + buf * XBUF;
        int gr = t * 128 + pr;
        if (gr < NN) {
            const __half* sh_ = &xh[(size_t)gr * 128 + ph * 32];
            #pragma unroll
            for (int i = 0; i < 4; i++)
                CP_ASYNC16(base + prel + i * 16, sh_ + i * 8);
        } else {
            uint4 z = make_uint4(0, 0, 0, 0);
            #pragma unroll
            for (int i = 0; i < 4; i++)
                *(uint4*)(sm + buf * XBUF + prel + i * 16) = z;
        }
    };

    prefetch(blockIdx.x, 0);
    CP_COMMIT();

    {
        const float4* s4h = (const float4*)Wh;
        float4* d4h = (float4*)(sm + W_OFF);
        for (int i = tid; i < WBYTES / 16; i += 512) d4h[i] = s4h[i];
    }

    const int m0 = (wid & 3) * 32;
    const int n0 = (wid >> 2) * NWTILE;
    const uint32_t aRel =
        (uint32_t)(((m0 + (lane & 15)) * XS + (lane >> 4) * 8) * 2);
    const uint32_t bH0 = smb + W_OFF +
        (uint32_t)(((n0 + (lane >> 4) * 8 + (lane & 7)) * XS + ((lane >> 3) & 1) * 8) * 2);

    const int g  = lane >> 2;
    const int tq = lane & 3;

    int buf = 0;
    for (int t = blockIdx.x; t < NTILES; t += gridDim.x, buf ^= 1) {
        const int row0 = t * 128;

        CP_WAIT0();
        __syncthreads();

        {
            int tn = t + gridDim.x;
            if (tn < NTILES) prefetch(tn, buf ^ 1);
            CP_COMMIT();
        }

        float acc[2][NFRAG][4];
        #pragma unroll
        for (int mi = 0; mi < 2; mi++)
            #pragma unroll
            for (int f = 0; f < NFRAG; f++)
                #pragma unroll
                for (int q = 0; q < 4; q++) acc[mi][f][q] = 0.f;

        uint32_t AHf[2][2][4];
        uint32_t BHf[2][NF2][4];

        uint32_t aH = smb + buf * XBUF + aRel;
        uint32_t bH = bH0;
        LDSM4(AHf[0][0], aH);
        LDSM4(AHf[0][1], aH + 16 * XS * 2);
        #pragma unroll
        for (int j = 0; j < NF2; j++)
            LDSM4(BHf[0][j], bH + j * 16 * XS * 2);

        #pragma unroll
        for (int ks = 0; ks < 8; ks++) {
            const int cur = ks & 1;
            const int nxt = cur ^ 1;
            if (ks < 7) {
                aH += 32; bH += 32;
                LDSM4(AHf[nxt][0], aH);
                LDSM4(AHf[nxt][1], aH + 16 * XS * 2);
                #pragma unroll
                for (int j = 0; j < NF2; j++)
                    LDSM4(BHf[nxt][j], bH + j * 16 * XS * 2);
            }
            #pragma unroll
            for (int mi = 0; mi < 2; mi++)
                #pragma unroll
                for (int j = 0; j < NF2; j++)
                    #pragma unroll
                    for (int h = 0; h < 2; h++)
                        MMA_F16(acc[mi][j * 2 + h], AHf[cur][mi],
                                BHf[cur][j][h * 2], BHf[cur][j][h * 2 + 1]);
        }

        #pragma unroll
        for (int mi = 0; mi < 2; mi++) {
            int r1 = row0 + m0 + mi * 16 + g;
            int r2 = r1 + 8;
            float s1 = (r1 < NN) ? g_norm_out[r1] : 0.f;
            float s2 = (r2 < NN) ? g_norm_out[r2] : 0.f;
            #pragma unroll
            for (int f = 0; f < NFRAG; f++) {
                int n = n0 + f * 8 + tq * 2;
                if (OUTC < NTILE && n >= OUTC) continue;
                float* c = acc[mi][f];
                if (r1 < NN) {
                    __half2 hv = __floats2half2_rn(c[0] * s1, c[1] * s1);
                    *(__half2*)&hout[(size_t)r1 * OUTC + n] = hv;
                }
                if (r2 < NN) {
                    __half2 hv = __floats2half2_rn(c[2] * s2, c[3] * s2);
                    *(__half2*)&hout[(size_t)r2 * OUTC + n] = hv;
                }
            }
        }
    }
}

// ===========================================================================
// Aggregation 128-dim: one warp per dst node, PAIR-EDGE layout (R16 form).
// ===========================================================================
__global__ void __launch_bounds__(256)
agg128(const float* __restrict__ bias, const __half* __restrict__ hsrc) {
    int w = (blockIdx.x * blockDim.x + threadIdx.x) >> 5;
    if (w >= NN) return;
    const int lane = threadIdx.x & 31;
    const int half = lane >> 4;        // 0 or 1
    const int hl   = lane & 15;        // dim block (8 dims each)
    const int beg = g_offs[w], end = g_offs[w + 1];

    float acc[8];
    #pragma unroll
    for (int j = 0; j < 8; j++) acc[j] = 0.f;

    int e = beg;
    for (; e + 4 <= end; e += 4) {
        int sA = g_csr[e + half];
        int sB = g_csr[e + 2 + half];
        uint4 uA = *(const uint4*)&hsrc[(size_t)sA * 128 + hl * 8];
        uint4 uB = *(const uint4*)&hsrc[(size_t)sB * 128 + hl * 8];
        float2 f0 = __half22float2(*(__half2*)&uA.x);
        float2 f1 = __half22float2(*(__half2*)&uA.y);
        float2 f2 = __half22float2(*(__half2*)&uA.z);
        float2 f3 = __half22float2(*(__half2*)&uA.w);
        float2 g0 = __half22float2(*(__half2*)&uB.x);
        float2 g1 = __half22float2(*(__half2*)&uB.y);
        float2 g2 = __half22float2(*(__half2*)&uB.z);
        float2 g3 = __half22float2(*(__half2*)&uB.w);
        acc[0] += f0.x + g0.x; acc[1] += f0.y + g0.y;
        acc[2] += f1.x + g1.x; acc[3] += f1.y + g1.y;
        acc[4] += f2.x + g2.x; acc[5] += f2.y + g2.y;
        acc[6] += f3.x + g3.x; acc[7] += f3.y + g3.y;
    }
    if (e + 2 <= end) {
        int sA = g_csr[e + half];
        uint4 uA = *(const uint4*)&hsrc[(size_t)sA * 128 + hl * 8];
        float2 f0 = __half22float2(*(__half2*)&uA.x);
        float2 f1 = __half22float2(*(__half2*)&uA.y);
        float2 f2 = __half22float2(*(__half2*)&uA.z);
        float2 f3 = __half22float2(*(__half2*)&uA.w);
        acc[0] += f0.x; acc[1] += f0.y; acc[2] += f1.x; acc[3] += f1.y;
        acc[4] += f2.x; acc[5] += f2.y; acc[6] += f3.x; acc[7] += f3.y;
        e += 2;
    }
    if (e < end && half == 0) {
        int sA = g_csr[e];
        uint4 uA = *(const uint4*)&hsrc[(size_t)sA * 128 + hl * 8];
        float2 f0 = __half22float2(*(__half2*)&uA.x);
        float2 f1 = __half22float2(*(__half2*)&uA.y);
        float2 f2 = __half22float2(*(__half2*)&uA.z);
        float2 f3 = __half22float2(*(__half2*)&uA.w);
        acc[0] += f0.x; acc[1] += f0.y; acc[2] += f1.x; acc[3] += f1.y;
        acc[4] += f2.x; acc[5] += f2.y; acc[6] += f3.x; acc[7] += f3.y;
    }

    #pragma unroll
    for (int j = 0; j < 8; j++)
        acc[j] += __shfl_xor_sync(0xffffffffu, acc[j], 16);

    if (half == 0) {
        float sc = g_norm_in[w];
        float4 b0 = *(const float4*)&bias[hl * 8];
        float4 b1 = *(const float4*)&bias[hl * 8 + 4];
        float o0 = fmaxf(fmaf(acc[0], sc, b0.x), 0.f);
        float o1 = fmaxf(fmaf(acc[1], sc, b0.y), 0.f);
        float o2 = fmaxf(fmaf(acc[2], sc, b0.z), 0.f);
        float o3 = fmaxf(fmaf(acc[3], sc, b0.w), 0.f);
        float o4 = fmaxf(fmaf(acc[4], sc, b1.x), 0.f);
        float o5 = fmaxf(fmaf(acc[5], sc, b1.y), 0.f);
        float o6 = fmaxf(fmaf(acc[6], sc, b1.z), 0.f);
        float o7 = fmaxf(fmaf(acc[7], sc, b1.w), 0.f);
        __half2 h0 = __floats2half2_rn(o0, o1);
        __half2 h1 = __floats2half2_rn(o2, o3);
        __half2 h2 = __floats2half2_rn(o4, o5);
        __half2 h3 = __floats2half2_rn(o6, o7);
        uint4 hv = make_uint4(*(uint32_t*)&h0, *(uint32_t*)&h1,
                              *(uint32_t*)&h2, *(uint32_t*)&h3);
        *(uint4*)&g_xh[(size_t)w * 128 + hl * 8] = hv;
    }
}

// ===========================================================================
// Aggregation 40-dim -> d_out (fp32). TRIPLE-EDGE layout: 3 edges/warp,
// 10 lanes x uint2 (4 dims) each; shfl_down(10/20) reduce; lanes 0-9 store.
// ===========================================================================
__global__ void __launch_bounds__(256)
agg40(const float* __restrict__ bias, const __half* __restrict__ hsrc,
      float* __restrict__ out) {
    int w = (blockIdx.x * blockDim.x + threadIdx.x) >> 5;
    if (w >= NN) return;
    const int lane = threadIdx.x & 31;
    const int grp  = lane / 10;        // 0,1,2 (lanes 30-31: grp 3, idle)
    const int gl   = lane % 10;        // 4-dim slot
    const int beg = g_offs[w], end = g_offs[w + 1];

    float acc[4] = {0.f, 0.f, 0.f, 0.f};
    if (grp < 3) {
        for (int base = beg; base < end; base += 3) {
            int idx = base + grp;
            int s = g_csr[idx < end ? idx : end - 1];
            uint2 u = *(const uint2*)&hsrc[(size_t)s * 40 + gl * 4];
            if (idx >= end) { u.x = 0u; u.y = 0u; }
            float2 f0 = __half22float2(*(__half2*)&u.x);
            float2 f1 = __half22float2(*(__half2*)&u.y);
            acc[0] += f0.x; acc[1] += f0.y; acc[2] += f1.x; acc[3] += f1.y;
        }
    }
    #pragma unroll
    for (int j = 0; j < 4; j++) {
        float t1 = __shfl_down_sync(0xffffffffu, acc[j], 10);
        float t2 = __shfl_down_sync(0xffffffffu, acc[j], 20);
        acc[j] += t1 + t2;
    }
    if (lane < 10) {
        float sc = g_norm_in[w];
        float4 o;
        o.x = fmaf(acc[0], sc, bias[gl * 4]);
        o.y = fmaf(acc[1], sc, bias[gl * 4 + 1]);
        o.z = fmaf(acc[2], sc, bias[gl * 4 + 2]);
        o.w = fmaf(acc[3], sc, bias[gl * 4 + 3]);
        *(float4*)&out[(size_t)w * 40 + gl * 4] = o;
    }
}

// ===========================================================================
extern "C" void kernel_launch(void* const* d_in, const int* in_sizes, int n_in,
                              void* d_out, int out_size) {
    const float* feat = (const float*)d_in[0];
    const int*   src  = (const int*)  d_in[1];
    const int*   dst  = (const int*)  d_in[2];
    const float* W0   = (const float*)d_in[3];
    const float* b0   = (const float*)d_in[4];
    const float* W1   = (const float*)d_in[5];
    const float* b1   = (const float*)d_in[6];
    const float* W2   = (const float*)d_in[7];
    const float* b2   = (const float*)d_in[8];
    float* out = (float*)d_out;

    const int NB = (NN + 255) / 256;
    const int EB = (EE + 255) / 256;
    const int SB = (NN + 1023) / 1024;
    const int AGGB = (NN * 32 + 255) / 256;
    const int FB = (NN * 32 + 255) / 256;

    const int SMEM_BIG   = 2 * 128 * 136 * 2 + 128 * 136 * 2;  // 104448
    const int SMEM_SMALL = 2 * 128 * 136 * 2 + 64 * 136 * 2;   // 87040

    static cudaStream_t s2 = nullptr;
    static cudaEvent_t evF = nullptr, evN = nullptr, evJ = nullptr;
    static bool init_done = false;
    if (!init_done) {
        cudaFuncSetAttribute(gemm_pers<128, 128>,
                             cudaFuncAttributeMaxDynamicSharedMemorySize, SMEM_BIG);
        cudaFuncSetAttribute(gemm_pers<64, 40>,
                             cudaFuncAttributeMaxDynamicSharedMemorySize, SMEM_SMALL);
        cudaStreamCreateWithFlags(&s2, cudaStreamNonBlocking);
        cudaEventCreateWithFlags(&evF, cudaEventDisableTiming);
        cudaEventCreateWithFlags(&evN, cudaEventDisableTiming);
        cudaEventCreateWithFlags(&evJ, cudaEventDisableTiming);
        init_done = true;
    }

    unsigned char *p_B0h, *p_B1h, *p_B2h;
    cudaGetSymbolAddress((void**)&p_B0h, g_B0h);
    cudaGetSymbolAddress((void**)&p_B1h, g_B1h);
    cudaGetSymbolAddress((void**)&p_B2h, g_B2h);
    __half* p_hbuf;
    __half* p_xh;
    cudaGetSymbolAddress((void**)&p_hbuf, g_hbuf);
    cudaGetSymbolAddress((void**)&p_xh, g_xh);

    // fork immediately: s2 runs input-only work (wtiles + feat convert),
    // then waits for norms and runs the layer-0 GEMM.
    cudaEventRecord(evF, 0);
    cudaStreamWaitEvent(s2, evF, 0);
    k_wtiles<<<(40960 + 255) / 256, 256, 0, s2>>>(W0, W1, W2);
    k_feat<<<FB, 256, 0, s2>>>(feat);

    // main stream: degree pipeline
    k_zero<<<NB, 256>>>();
    k_deg<<<EB, 256>>>(src, dst);
    k_norm<<<NB, 256>>>();
    cudaEventRecord(evN, 0);

    // s2: layer-0 GEMM (needs xh, Wtiles, norm_out)
    cudaStreamWaitEvent(s2, evN, 0);
    gemm_pers<128, 128><<<PGRID, 512, SMEM_BIG, s2>>>(p_xh, p_B0h, p_hbuf);
    cudaEventRecord(evJ, s2);

    // main stream: CSR build (concurrent with gemm0)
    k_scan1<<<SB, 1024>>>();
    k_scan2<<<1, 128>>>(SB);
    k_scan3<<<NB, 256>>>();
    k_scatter<<<EB, 256>>>(src, dst);
    cudaStreamWaitEvent(0, evJ, 0);

    // layer 0 aggregation (writes g_xh for next GEMM)
    agg128<<<AGGB, 256>>>(b0, p_hbuf);
    // layer 1
    gemm_pers<128, 128><<<PGRID, 512, SMEM_BIG>>>(p_xh, p_B1h, p_hbuf);
    agg128<<<AGGB, 256>>>(b1, p_hbuf);
    // layer 2
    gemm_pers<64, 40><<<PGRID, 512, SMEM_SMALL>>>(p_xh, p_B2h, p_hbuf);
    agg40<<<AGGB, 256>>>(b2, p_hbuf, out);
}